// round 1
// baseline (speedup 1.0000x reference)
#include <cuda_runtime.h>
#include <math.h>

#define Bc   4
#define Sc   2048
#define Dc   2048
#define LATc 512
#define NHc  16
#define NKVc 4
#define HDc  32
#define KVDc 128
#define Tc   (Bc * Sc)
#define GAINc 0.25f
#define EPSc  1e-6f

// -------- scratch (device globals; no allocation allowed) --------
__device__ float g_q [Tc * LATc];
__device__ float g_k [Tc * KVDc];
__device__ float g_v [Tc * KVDc];
__device__ float g_qc[Tc * LATc];
__device__ float g_kc[Tc * KVDc];
__device__ float g_qm[Tc * HDc];
__device__ float g_km[Tc * HDc];
__device__ float g_o [Tc * LATc];

// ============================================================
// SGEMM: C[M,N] = A[M,K] * B[N,K]^T   (all row-major, fp32)
// M % 128 == 0, N % 128 == 0, K % 8 == 0 (true for all 4 uses)
// ============================================================
__global__ void __launch_bounds__(256) sgemm_abt(
    float* __restrict__ C, const float* __restrict__ A,
    const float* __restrict__ B, int M, int N, int K)
{
    __shared__ float As[8][128];
    __shared__ float Bs[8][128];
    const int tid = threadIdx.x;
    const int m0 = blockIdx.y * 128;
    const int n0 = blockIdx.x * 128;
    const int lr = tid >> 1;          // 0..127
    const int lc = (tid & 1) * 4;     // 0 or 4
    const int ty = tid >> 4;          // 0..15
    const int tx = tid & 15;          // 0..15

    float acc[8][8];
#pragma unroll
    for (int i = 0; i < 8; i++)
#pragma unroll
        for (int j = 0; j < 8; j++) acc[i][j] = 0.f;

    for (int kt = 0; kt < K; kt += 8) {
        float4 av = *(const float4*)(A + (size_t)(m0 + lr) * K + kt + lc);
        float4 bv = *(const float4*)(B + (size_t)(n0 + lr) * K + kt + lc);
        As[lc + 0][lr] = av.x; As[lc + 1][lr] = av.y;
        As[lc + 2][lr] = av.z; As[lc + 3][lr] = av.w;
        Bs[lc + 0][lr] = bv.x; Bs[lc + 1][lr] = bv.y;
        Bs[lc + 2][lr] = bv.z; Bs[lc + 3][lr] = bv.w;
        __syncthreads();
#pragma unroll
        for (int kk = 0; kk < 8; kk++) {
            float a[8], b[8];
            float4 a0 = *(const float4*)&As[kk][ty * 8];
            float4 a1 = *(const float4*)&As[kk][ty * 8 + 4];
            float4 b0 = *(const float4*)&Bs[kk][tx * 8];
            float4 b1 = *(const float4*)&Bs[kk][tx * 8 + 4];
            a[0]=a0.x; a[1]=a0.y; a[2]=a0.z; a[3]=a0.w;
            a[4]=a1.x; a[5]=a1.y; a[6]=a1.z; a[7]=a1.w;
            b[0]=b0.x; b[1]=b0.y; b[2]=b0.z; b[3]=b0.w;
            b[4]=b1.x; b[5]=b1.y; b[6]=b1.z; b[7]=b1.w;
#pragma unroll
            for (int i = 0; i < 8; i++)
#pragma unroll
                for (int j = 0; j < 8; j++)
                    acc[i][j] += a[i] * b[j];
        }
        __syncthreads();
    }

#pragma unroll
    for (int i = 0; i < 8; i++) {
        float* crow = C + (size_t)(m0 + ty * 8 + i) * N + n0 + tx * 8;
        float4 c0 = make_float4(acc[i][0], acc[i][1], acc[i][2], acc[i][3]);
        float4 c1 = make_float4(acc[i][4], acc[i][5], acc[i][6], acc[i][7]);
        *(float4*)(crow)     = c0;
        *(float4*)(crow + 4) = c1;
    }
}

// ============================================================
// In-place RMS norm over last dim C, one block per row
// ============================================================
__global__ void __launch_bounds__(128) rms_ip(
    float* __restrict__ x, const float* __restrict__ g, int C)
{
    const int t = blockIdx.x;
    float* row = x + (size_t)t * C;
    const int tid = threadIdx.x;
    float ss = 0.f;
    for (int i = tid; i < C; i += 128) { float v = row[i]; ss += v * v; }
#pragma unroll
    for (int o = 16; o; o >>= 1) ss += __shfl_xor_sync(~0u, ss, o);
    __shared__ float ws[4];
    if ((tid & 31) == 0) ws[tid >> 5] = ss;
    __syncthreads();
    float tot = ws[0] + ws[1] + ws[2] + ws[3];
    float r = rsqrtf(tot / (float)C + EPSc);
    for (int i = tid; i < C; i += 128) row[i] = row[i] * r * g[i];
}

// ============================================================
// Grouped causal conv, K=3, 32 in-channels per group,
// 32 out-channels per group (holds for both Q and K paths)
// w layout: [C][32][3]
// ============================================================
__global__ void __launch_bounds__(256) conv_causal(
    float* __restrict__ y, const float* __restrict__ x,
    const float* __restrict__ w, int C)
{
    const int idx = blockIdx.x * 256 + threadIdx.x;
    const int t = idx / C;
    const int c = idx - t * C;
    if (t >= Tc) return;
    const int s = t & (Sc - 1);
    const int base_in = (c >> 5) << 5;
    float acc = 0.f;
#pragma unroll
    for (int j = 0; j < 3; j++) {
        int sj = s - 2 + j;
        if (sj >= 0) {
            const float* xr = x + (size_t)(t - s + sj) * C + base_in;
            const float* wr = w + (size_t)c * 96 + j;
#pragma unroll
            for (int ci = 0; ci < 32; ci++)
                acc += wr[ci * 3] * xr[ci];
        }
    }
    y[idx] = acc;
}

// ============================================================
// Per-token head-mean: out[t][d] = mean_h x[t][h*32+d]
// ============================================================
__global__ void __launch_bounds__(256) head_mean(
    float* __restrict__ out, const float* __restrict__ x, int C, int heads)
{
    const int idx = blockIdx.x * 256 + threadIdx.x;
    if (idx >= Tc * HDc) return;
    const int t = idx >> 5;
    const int d = idx & 31;
    const float* row = x + (size_t)t * C + d;
    float s = 0.f;
    for (int h = 0; h < heads; h++) s += row[h * 32];
    out[idx] = s / (float)heads;
}

// x[t][c] += GAIN * mean[t][c & 31]
__global__ void __launch_bounds__(256) add_mean(
    float* __restrict__ x, const float* __restrict__ mean, int C)
{
    const int idx = blockIdx.x * 256 + threadIdx.x;
    const int t = idx / C;
    if (t >= Tc) return;
    const int d = idx & 31;
    x[idx] += GAINc * mean[(t << 5) + d];
}

// ============================================================
// Per-head L2 normalize (+temp) then RoPE, in place.
// For Q: factor = 1/norm  (the sqrt(HD) cancels the attention scale)
// For K: factor = sqrt(HD)*key_temp/norm
// ============================================================
__global__ void __launch_bounds__(128) headnorm_rope(
    float* __restrict__ x, int C, const float* __restrict__ key_temp, int is_k)
{
    const int nh = C >> 5;
    const int idx = blockIdx.x * 128 + threadIdx.x;
    const int t = idx / nh;
    if (t >= Tc) return;
    const int h = idx - t * nh;
    const int s = t & (Sc - 1);
    float* p = x + (size_t)t * C + h * 32;
    float v[32];
    float ss = 0.f;
#pragma unroll
    for (int d = 0; d < 32; d++) { v[d] = p[d]; ss += v[d] * v[d]; }
    float n = fmaxf(sqrtf(ss), 1e-12f);
    float f = is_k ? (5.656854249492380f * key_temp[0] / n) : (1.0f / n);
#pragma unroll
    for (int d = 0; d < 32; d++) v[d] *= f;
#pragma unroll
    for (int i = 0; i < 16; i++) {
        // freq_i = 10000^(-i/16) = exp(-i*ln(10000)/16)
        float fr = expf(-(float)i * 0.575646273248511f);
        float ang = (float)s * fr;
        float sn, cs;
        sincosf(ang, &sn, &cs);
        float x1 = v[2 * i], x2 = v[2 * i + 1];
        v[2 * i]     = x1 * cs - x2 * sn;
        v[2 * i + 1] = x1 * sn + x2 * cs;
    }
#pragma unroll
    for (int d = 0; d < 32; d++) p[d] = v[d];
}

// ============================================================
// Flash-style causal attention (GQA 16 q-heads -> 4 kv-heads)
// One thread per query row; 32-key smem tiles.
// q layout [t, 16*32], k/v layout [t, 4*32]; out [t, 16*32]
// Scale already folded into q normalization.
// ============================================================
__global__ void __launch_bounds__(128) flash_attn(
    float* __restrict__ o, const float* __restrict__ q,
    const float* __restrict__ k, const float* __restrict__ v)
{
    __shared__ float Ks[32][32];
    __shared__ float Vs[32][32];
    const int bh = blockIdx.y;
    const int b = bh / NHc;
    const int h = bh - b * NHc;
    const int kh = h >> 2;                  // n_groups = 4
    const int tid = threadIdx.x;
    const int sq = blockIdx.x * 128 + tid;  // query position

    float qr[32];
    {
        const float* qp = q + (size_t)(b * Sc + sq) * LATc + h * 32;
#pragma unroll
        for (int d = 0; d < 32; d++) qr[d] = qp[d];
    }
    float oacc[32];
#pragma unroll
    for (int d = 0; d < 32; d++) oacc[d] = 0.f;
    float m = -1e30f, l = 0.f;

    const int maxs = blockIdx.x * 128 + 127;
    const int ntiles = (maxs >> 5) + 1;

    for (int jt = 0; jt < ntiles; jt++) {
        const int j0 = jt << 5;
        __syncthreads();
        // load K/V tile (32 rows x 32 dims)
        for (int u = tid; u < 1024; u += 128) {
            int jj = u >> 5, d = u & 31;
            size_t gi = (size_t)(b * Sc + j0 + jj) * KVDc + kh * 32 + d;
            Ks[jj][d] = k[gi];
            Vs[jj][d] = v[gi];
        }
        __syncthreads();
        if (j0 <= sq) {
            float sc[32];
#pragma unroll
            for (int j = 0; j < 32; j++) {
                float s = 0.f;
#pragma unroll
                for (int d = 0; d < 32; d++) s += qr[d] * Ks[j][d];
                sc[j] = s;
            }
#pragma unroll
            for (int j = 0; j < 32; j++)
                if (j0 + j > sq) sc[j] = -1e30f;
            float tm = m;
#pragma unroll
            for (int j = 0; j < 32; j++) tm = fmaxf(tm, sc[j]);
            float alpha = __expf(m - tm);
            m = tm;
            l *= alpha;
#pragma unroll
            for (int d = 0; d < 32; d++) oacc[d] *= alpha;
#pragma unroll
            for (int j = 0; j < 32; j++) {
                float p = __expf(sc[j] - m);
                l += p;
#pragma unroll
                for (int d = 0; d < 32; d++) oacc[d] += p * Vs[j][d];
            }
        }
    }

    float inv = 1.0f / l;
    float* op = o + (size_t)(b * Sc + sq) * LATc + h * 32;
#pragma unroll
    for (int d = 0; d < 32; d++) op[d] = oacc[d] * inv;
}

// ============================================================
// host launcher
// ============================================================
extern "C" void kernel_launch(void* const* d_in, const int* in_sizes, int n_in,
                              void* d_out, int out_size)
{
    const float* x        = (const float*)d_in[0];
    const float* w_q      = (const float*)d_in[1];
    const float* w_k      = (const float*)d_in[2];
    const float* w_v      = (const float*)d_in[3];
    const float* g_latent = (const float*)d_in[4];
    const float* g_kv     = (const float*)d_in[5];
    const float* conv_q_w = (const float*)d_in[6];
    const float* conv_k_w = (const float*)d_in[7];
    const float* g_conv   = (const float*)d_in[8];
    const float* g_kconv  = (const float*)d_in[9];
    const float* g_postq  = (const float*)d_in[10];
    const float* g_postk  = (const float*)d_in[11];
    const float* key_temp = (const float*)d_in[12];
    const float* g_preout = (const float*)d_in[13];
    const float* w_o      = (const float*)d_in[14];
    float* out = (float*)d_out;

    float *pq, *pk, *pv, *pqc, *pkc, *pqm, *pkm, *po;
    cudaGetSymbolAddress((void**)&pq,  g_q);
    cudaGetSymbolAddress((void**)&pk,  g_k);
    cudaGetSymbolAddress((void**)&pv,  g_v);
    cudaGetSymbolAddress((void**)&pqc, g_qc);
    cudaGetSymbolAddress((void**)&pkc, g_kc);
    cudaGetSymbolAddress((void**)&pqm, g_qm);
    cudaGetSymbolAddress((void**)&pkm, g_km);
    cudaGetSymbolAddress((void**)&po,  g_o);

    // 1) projections
    sgemm_abt<<<dim3(LATc / 128, Tc / 128), 256>>>(pq, x, w_q, Tc, LATc, Dc);
    sgemm_abt<<<dim3(KVDc / 128, Tc / 128), 256>>>(pk, x, w_k, Tc, KVDc, Dc);
    sgemm_abt<<<dim3(KVDc / 128, Tc / 128), 256>>>(pv, x, w_v, Tc, KVDc, Dc);

    // 2) first RMS norms
    rms_ip<<<Tc, 128>>>(pq, g_latent, LATc);
    rms_ip<<<Tc, 128>>>(pk, g_kv, KVDc);
    rms_ip<<<Tc, 128>>>(pv, g_kv, KVDc);

    // 3) causal grouped conv + RMS
    conv_causal<<<(Tc * LATc) / 256, 256>>>(pqc, pq, conv_q_w, LATc);
    conv_causal<<<(Tc * KVDc) / 256, 256>>>(pkc, pk, conv_k_w, KVDc);
    rms_ip<<<Tc, 128>>>(pqc, g_conv, LATc);
    rms_ip<<<Tc, 128>>>(pkc, g_kconv, KVDc);

    // 4) cross-coupling means (from pre-conv q/k)
    head_mean<<<(Tc * HDc) / 256, 256>>>(pqm, pq, LATc, NHc);
    head_mean<<<(Tc * HDc) / 256, 256>>>(pkm, pk, KVDc, NKVc);
    add_mean<<<(Tc * LATc) / 256, 256>>>(pqc, pkm, LATc);
    add_mean<<<(Tc * KVDc) / 256, 256>>>(pkc, pqm, KVDc);

    // 5) post RMS
    rms_ip<<<Tc, 128>>>(pqc, g_postq, LATc);
    rms_ip<<<Tc, 128>>>(pkc, g_postk, KVDc);

    // 6) per-head L2 norm + RoPE (attn scale folded into q)
    headnorm_rope<<<(Tc * NHc) / 128, 128>>>(pqc, LATc, key_temp, 0);
    headnorm_rope<<<(Tc * NKVc) / 128, 128>>>(pkc, KVDc, key_temp, 1);

    // 7) causal attention
    flash_attn<<<dim3(Sc / 128, Bc * NHc), 128>>>(po, pqc, pkc, pv);

    // 8) pre-out RMS + output projection
    rms_ip<<<Tc, 128>>>(po, g_preout, LATc);
    sgemm_abt<<<dim3(Dc / 128, Tc / 128), 256>>>(out, po, w_o, Tc, Dc, LATc);
}

// round 3
// speedup vs baseline: 1.2506x; 1.2506x over previous
#include <cuda_runtime.h>
#include <math.h>
#include <cstdint>

#define Bc   4
#define Sc   2048
#define Dc   2048
#define LATc 512
#define NHc  16
#define NKVc 4
#define HDc  32
#define KVDc 128
#define Tc   (Bc * Sc)
#define GAINc 0.25f
#define EPSc  1e-6f

// -------- scratch (device globals; no allocation allowed) --------
__device__ float g_q [Tc * LATc];
__device__ float g_k [Tc * KVDc];
__device__ float g_v [Tc * KVDc];
__device__ float g_qc[Tc * LATc];
__device__ float g_kc[Tc * KVDc];
__device__ float g_qm[Tc * HDc];
__device__ float g_km[Tc * HDc];
__device__ float g_o [Tc * LATc];

// ---------------- mma.sync helpers (sm_80+ path; works on plain sm_103) ----
__device__ __forceinline__ void mma_tf32(float* d, uint32_t a0, uint32_t a1,
                                         uint32_t a2, uint32_t a3,
                                         uint32_t b0, uint32_t b1) {
    asm volatile(
        "mma.sync.aligned.m16n8k8.row.col.f32.tf32.tf32.f32 "
        "{%0,%1,%2,%3}, {%4,%5,%6,%7}, {%8,%9}, {%0,%1,%2,%3};"
        : "+f"(d[0]), "+f"(d[1]), "+f"(d[2]), "+f"(d[3])
        : "r"(a0), "r"(a1), "r"(a2), "r"(a3), "r"(b0), "r"(b1));
}
__device__ __forceinline__ void split_tf32(float x, uint32_t& hi, uint32_t& lo) {
    uint32_t h;
    asm("cvt.rna.tf32.f32 %0, %1;" : "=r"(h) : "f"(x));
    float r = x - __uint_as_float(h);
    uint32_t l;
    asm("cvt.rna.tf32.f32 %0, %1;" : "=r"(l) : "f"(r));
    hi = h; lo = l;
}
__device__ __forceinline__ uint32_t smem_u32(const void* p) {
    uint32_t a;
    asm("{ .reg .u64 t; cvta.to.shared.u64 t, %1; cvt.u32.u64 %0, t; }" : "=r"(a) : "l"(p));
    return a;
}
#define CP_ASYNC16(dst, src) \
    asm volatile("cp.async.cg.shared.global [%0], [%1], 16;" :: "r"(dst), "l"(src))
#define CP_COMMIT() asm volatile("cp.async.commit_group;" ::: "memory")
#define CP_WAIT(n)  asm volatile("cp.async.wait_group %0;" :: "n"(n) : "memory")

// ============================================================
// tf32-split GEMM via mma.sync: C[M,N] = A[M,K]*B[N,K]^T (fp32 in/out)
// CTA tile 128x128, K-chunk 32, 2-stage cp.async pipeline.
// Fused multi-output: bx<nx0 -> (B0,C0,N0); bx==nx0 -> (B1,C1,128);
// bx==nx0+1 -> (B2,C2,128).
// ============================================================
#define TSTRIDE 36                       // floats per smem row (pad: conflict-free frags)
#define ABYTES  (128 * TSTRIDE * 4)      // 18432
#define BUFB    (2 * ABYTES)             // A + B per stage
#define GEMM_SMEM (2 * BUFB)             // two stages: 73728 B

__global__ void __launch_bounds__(256, 1) gemm_tf32(
    const float* __restrict__ A, int K,
    const float* __restrict__ B0, float* __restrict__ C0, int nx0, int N0,
    const float* __restrict__ B1, float* __restrict__ C1,
    const float* __restrict__ B2, float* __restrict__ C2)
{
    extern __shared__ char sm[];
    const int tid = threadIdx.x;
    const int wid = tid >> 5;
    const int lane = tid & 31;
    const int lr = lane >> 2;       // 0..7
    const int lc = lane & 3;        // 0..3
    const int wm = wid & 3;         // warp row (M): 0..3, tile 32
    const int wn = wid >> 2;        // warp col (N): 0..1, tile 64

    int bx = blockIdx.x;
    const float* Bp;
    float* Cp;
    int N;
    if (bx < nx0)       { Bp = B0; Cp = C0; N = N0; }
    else if (bx == nx0) { Bp = B1; Cp = C1; N = 128; bx = 0; }
    else                { Bp = B2; Cp = C2; N = 128; bx = 0; }
    const int m0 = blockIdx.y * 128;
    const int n0 = bx * 128;
    const int NC = K >> 5;

    // global->smem geometry: 1024 16B segments per matrix per chunk, 4 per thread
    // seg = tid + j*256 ; row = seg>>3 ; c16 = seg&7
    const uint32_t smb = smem_u32(sm);
    int grow[4], gc16[4];
    uint32_t sdst[4];
#pragma unroll
    for (int j = 0; j < 4; j++) {
        int seg = tid + j * 256;
        grow[j] = seg >> 3;
        gc16[j] = seg & 7;
        sdst[j] = (uint32_t)(grow[j] * (TSTRIDE * 4) + gc16[j] * 16);
    }

    float acc[2][8][4];
#pragma unroll
    for (int mt = 0; mt < 2; mt++)
#pragma unroll
        for (int nt = 0; nt < 8; nt++)
#pragma unroll
            for (int c = 0; c < 4; c++) acc[mt][nt][c] = 0.f;

    // prefetch chunk 0 into stage 0
#pragma unroll
    for (int j = 0; j < 4; j++) {
        CP_ASYNC16(smb + sdst[j],
                   A + (size_t)(m0 + grow[j]) * K + gc16[j] * 4);
        CP_ASYNC16(smb + ABYTES + sdst[j],
                   Bp + (size_t)(n0 + grow[j]) * K + gc16[j] * 4);
    }
    CP_COMMIT();

    for (int i = 0; i < NC; i++) {
        if (i + 1 < NC) {
            const uint32_t so = smb + (uint32_t)((i + 1) & 1) * BUFB;
            const int kt = (i + 1) << 5;
#pragma unroll
            for (int j = 0; j < 4; j++) {
                CP_ASYNC16(so + sdst[j],
                           A + (size_t)(m0 + grow[j]) * K + kt + gc16[j] * 4);
                CP_ASYNC16(so + ABYTES + sdst[j],
                           Bp + (size_t)(n0 + grow[j]) * K + kt + gc16[j] * 4);
            }
            CP_COMMIT();
            CP_WAIT(1);
        } else {
            CP_WAIT(0);
        }
        __syncthreads();

        const float* Ab = (const float*)(sm + (size_t)(i & 1) * BUFB);
        const float* Bb = (const float*)(sm + (size_t)(i & 1) * BUFB + ABYTES);

#pragma unroll
        for (int ks = 0; ks < 4; ks++) {
            const int kc = ks * 8 + lc;
            uint32_t ah[2][4], al[2][4];
#pragma unroll
            for (int mt = 0; mt < 2; mt++) {
                const int r = wm * 32 + mt * 16 + lr;
                float a0 = Ab[r * TSTRIDE + kc];
                float a1 = Ab[(r + 8) * TSTRIDE + kc];
                float a2 = Ab[r * TSTRIDE + kc + 4];
                float a3 = Ab[(r + 8) * TSTRIDE + kc + 4];
                split_tf32(a0, ah[mt][0], al[mt][0]);
                split_tf32(a1, ah[mt][1], al[mt][1]);
                split_tf32(a2, ah[mt][2], al[mt][2]);
                split_tf32(a3, ah[mt][3], al[mt][3]);
            }
            uint32_t bh[8][2], bl[8][2];
#pragma unroll
            for (int nt = 0; nt < 8; nt++) {
                const int n = wn * 64 + nt * 8 + lr;
                float b0 = Bb[n * TSTRIDE + kc];
                float b1 = Bb[n * TSTRIDE + kc + 4];
                split_tf32(b0, bh[nt][0], bl[nt][0]);
                split_tf32(b1, bh[nt][1], bl[nt][1]);
            }
#pragma unroll
            for (int mt = 0; mt < 2; mt++)
#pragma unroll
                for (int nt = 0; nt < 8; nt++) {
                    mma_tf32(acc[mt][nt], ah[mt][0], ah[mt][1], ah[mt][2], ah[mt][3],
                             bh[nt][0], bh[nt][1]);
                    mma_tf32(acc[mt][nt], ah[mt][0], ah[mt][1], ah[mt][2], ah[mt][3],
                             bl[nt][0], bl[nt][1]);
                    mma_tf32(acc[mt][nt], al[mt][0], al[mt][1], al[mt][2], al[mt][3],
                             bh[nt][0], bh[nt][1]);
                }
        }
        __syncthreads();
    }

    // epilogue
#pragma unroll
    for (int mt = 0; mt < 2; mt++) {
        const int r = m0 + wm * 32 + mt * 16 + lr;
#pragma unroll
        for (int nt = 0; nt < 8; nt++) {
            const int cN = n0 + wn * 64 + nt * 8 + 2 * lc;
            *(float2*)(Cp + (size_t)r * N + cN) =
                make_float2(acc[mt][nt][0], acc[mt][nt][1]);
            *(float2*)(Cp + (size_t)(r + 8) * N + cN) =
                make_float2(acc[mt][nt][2], acc[mt][nt][3]);
        }
    }
}

// ============================================================
// In-place RMS norm over last dim C, one block per row
// ============================================================
__global__ void __launch_bounds__(128) rms_ip(
    float* __restrict__ x, const float* __restrict__ g, int C)
{
    const int t = blockIdx.x;
    float* row = x + (size_t)t * C;
    const int tid = threadIdx.x;
    float ss = 0.f;
    for (int i = tid; i < C; i += 128) { float v = row[i]; ss += v * v; }
#pragma unroll
    for (int o = 16; o; o >>= 1) ss += __shfl_xor_sync(~0u, ss, o);
    __shared__ float ws[4];
    if ((tid & 31) == 0) ws[tid >> 5] = ss;
    __syncthreads();
    float tot = ws[0] + ws[1] + ws[2] + ws[3];
    float r = rsqrtf(tot / (float)C + EPSc);
    for (int i = tid; i < C; i += 128) row[i] = row[i] * r * g[i];
}

// ============================================================
// Grouped causal conv, K=3, 32 in/out channels per group
// w layout: [C][32][3]
// ============================================================
__global__ void __launch_bounds__(256) conv_causal(
    float* __restrict__ y, const float* __restrict__ x,
    const float* __restrict__ w, int C)
{
    const int idx = blockIdx.x * 256 + threadIdx.x;
    const int t = idx / C;
    const int c = idx - t * C;
    if (t >= Tc) return;
    const int s = t & (Sc - 1);
    const int base_in = (c >> 5) << 5;
    float acc = 0.f;
#pragma unroll
    for (int j = 0; j < 3; j++) {
        int sj = s - 2 + j;
        if (sj >= 0) {
            const float* xr = x + (size_t)(t - s + sj) * C + base_in;
            const float* wr = w + (size_t)c * 96 + j;
#pragma unroll
            for (int ci = 0; ci < 32; ci++)
                acc += wr[ci * 3] * xr[ci];
        }
    }
    y[idx] = acc;
}

// ============================================================
// Per-token head-mean: out[t][d] = mean_h x[t][h*32+d]
// ============================================================
__global__ void __launch_bounds__(256) head_mean(
    float* __restrict__ out, const float* __restrict__ x, int C, int heads)
{
    const int idx = blockIdx.x * 256 + threadIdx.x;
    if (idx >= Tc * HDc) return;
    const int t = idx >> 5;
    const int d = idx & 31;
    const float* row = x + (size_t)t * C + d;
    float s = 0.f;
    for (int h = 0; h < heads; h++) s += row[h * 32];
    out[idx] = s / (float)heads;
}

__global__ void __launch_bounds__(256) add_mean(
    float* __restrict__ x, const float* __restrict__ mean, int C)
{
    const int idx = blockIdx.x * 256 + threadIdx.x;
    const int t = idx / C;
    if (t >= Tc) return;
    const int d = idx & 31;
    x[idx] += GAINc * mean[(t << 5) + d];
}

// ============================================================
// Per-head L2 normalize (+temp) then RoPE, in place.
// ============================================================
__global__ void __launch_bounds__(128) headnorm_rope(
    float* __restrict__ x, int C, const float* __restrict__ key_temp, int is_k)
{
    const int nh = C >> 5;
    const int idx = blockIdx.x * 128 + threadIdx.x;
    const int t = idx / nh;
    if (t >= Tc) return;
    const int h = idx - t * nh;
    const int s = t & (Sc - 1);
    float* p = x + (size_t)t * C + h * 32;
    float v[32];
    float ss = 0.f;
#pragma unroll
    for (int d = 0; d < 32; d++) { v[d] = p[d]; ss += v[d] * v[d]; }
    float n = fmaxf(sqrtf(ss), 1e-12f);
    float f = is_k ? (5.656854249492380f * key_temp[0] / n) : (1.0f / n);
#pragma unroll
    for (int d = 0; d < 32; d++) v[d] *= f;
#pragma unroll
    for (int i = 0; i < 16; i++) {
        float fr = expf(-(float)i * 0.575646273248511f);
        float ang = (float)s * fr;
        float sn, cs;
        sincosf(ang, &sn, &cs);
        float x1 = v[2 * i], x2 = v[2 * i + 1];
        v[2 * i]     = x1 * cs - x2 * sn;
        v[2 * i + 1] = x1 * sn + x2 * cs;
    }
#pragma unroll
    for (int d = 0; d < 32; d++) p[d] = v[d];
}

// ============================================================
// Flash-style causal attention (GQA 16 q-heads -> 4 kv-heads)
// ============================================================
__global__ void __launch_bounds__(128) flash_attn(
    float* __restrict__ o, const float* __restrict__ q,
    const float* __restrict__ k, const float* __restrict__ v)
{
    __shared__ float Ks[32][32];
    __shared__ float Vs[32][32];
    const int bh = blockIdx.y;
    const int b = bh / NHc;
    const int h = bh - b * NHc;
    const int kh = h >> 2;
    const int tid = threadIdx.x;
    const int sq = blockIdx.x * 128 + tid;

    float qr[32];
    {
        const float* qp = q + (size_t)(b * Sc + sq) * LATc + h * 32;
#pragma unroll
        for (int d = 0; d < 32; d++) qr[d] = qp[d];
    }
    float oacc[32];
#pragma unroll
    for (int d = 0; d < 32; d++) oacc[d] = 0.f;
    float m = -1e30f, l = 0.f;

    const int maxs = blockIdx.x * 128 + 127;
    const int ntiles = (maxs >> 5) + 1;

    for (int jt = 0; jt < ntiles; jt++) {
        const int j0 = jt << 5;
        __syncthreads();
        for (int u = tid; u < 1024; u += 128) {
            int jj = u >> 5, d = u & 31;
            size_t gi = (size_t)(b * Sc + j0 + jj) * KVDc + kh * 32 + d;
            Ks[jj][d] = k[gi];
            Vs[jj][d] = v[gi];
        }
        __syncthreads();
        if (j0 <= sq) {
            float sc[32];
#pragma unroll
            for (int j = 0; j < 32; j++) {
                float s = 0.f;
#pragma unroll
                for (int d = 0; d < 32; d++) s += qr[d] * Ks[j][d];
                sc[j] = s;
            }
#pragma unroll
            for (int j = 0; j < 32; j++)
                if (j0 + j > sq) sc[j] = -1e30f;
            float tm = m;
#pragma unroll
            for (int j = 0; j < 32; j++) tm = fmaxf(tm, sc[j]);
            float alpha = __expf(m - tm);
            m = tm;
            l *= alpha;
#pragma unroll
            for (int d = 0; d < 32; d++) oacc[d] *= alpha;
#pragma unroll
            for (int j = 0; j < 32; j++) {
                float p = __expf(sc[j] - m);
                l += p;
#pragma unroll
                for (int d = 0; d < 32; d++) oacc[d] += p * Vs[j][d];
            }
        }
    }

    float inv = 1.0f / l;
    float* op = o + (size_t)(b * Sc + sq) * LATc + h * 32;
#pragma unroll
    for (int d = 0; d < 32; d++) op[d] = oacc[d] * inv;
}

// ============================================================
// host launcher
// ============================================================
extern "C" void kernel_launch(void* const* d_in, const int* in_sizes, int n_in,
                              void* d_out, int out_size)
{
    const float* x        = (const float*)d_in[0];
    const float* w_q      = (const float*)d_in[1];
    const float* w_k      = (const float*)d_in[2];
    const float* w_v      = (const float*)d_in[3];
    const float* g_latent = (const float*)d_in[4];
    const float* g_kv     = (const float*)d_in[5];
    const float* conv_q_w = (const float*)d_in[6];
    const float* conv_k_w = (const float*)d_in[7];
    const float* g_conv   = (const float*)d_in[8];
    const float* g_kconv  = (const float*)d_in[9];
    const float* g_postq  = (const float*)d_in[10];
    const float* g_postk  = (const float*)d_in[11];
    const float* key_temp = (const float*)d_in[12];
    const float* g_preout = (const float*)d_in[13];
    const float* w_o      = (const float*)d_in[14];
    float* out = (float*)d_out;

    float *pq, *pk, *pv, *pqc, *pkc, *pqm, *pkm, *po;
    cudaGetSymbolAddress((void**)&pq,  g_q);
    cudaGetSymbolAddress((void**)&pk,  g_k);
    cudaGetSymbolAddress((void**)&pv,  g_v);
    cudaGetSymbolAddress((void**)&pqc, g_qc);
    cudaGetSymbolAddress((void**)&pkc, g_kc);
    cudaGetSymbolAddress((void**)&pqm, g_qm);
    cudaGetSymbolAddress((void**)&pkm, g_km);
    cudaGetSymbolAddress((void**)&po,  g_o);

    cudaFuncSetAttribute(gemm_tf32, cudaFuncAttributeMaxDynamicSharedMemorySize, GEMM_SMEM);

    // 1) fused q/k/v projections
    gemm_tf32<<<dim3(6, Tc / 128), 256, GEMM_SMEM>>>(
        x, Dc, w_q, pq, 4, LATc, w_k, pk, w_v, pv);

    // 2) first RMS norms
    rms_ip<<<Tc, 128>>>(pq, g_latent, LATc);
    rms_ip<<<Tc, 128>>>(pk, g_kv, KVDc);
    rms_ip<<<Tc, 128>>>(pv, g_kv, KVDc);

    // 3) causal grouped conv + RMS
    conv_causal<<<(Tc * LATc) / 256, 256>>>(pqc, pq, conv_q_w, LATc);
    conv_causal<<<(Tc * KVDc) / 256, 256>>>(pkc, pk, conv_k_w, KVDc);
    rms_ip<<<Tc, 128>>>(pqc, g_conv, LATc);
    rms_ip<<<Tc, 128>>>(pkc, g_kconv, KVDc);

    // 4) cross-coupling means (from pre-conv q/k)
    head_mean<<<(Tc * HDc) / 256, 256>>>(pqm, pq, LATc, NHc);
    head_mean<<<(Tc * HDc) / 256, 256>>>(pkm, pk, KVDc, NKVc);
    add_mean<<<(Tc * LATc) / 256, 256>>>(pqc, pkm, LATc);
    add_mean<<<(Tc * KVDc) / 256, 256>>>(pkc, pqm, KVDc);

    // 5) post RMS
    rms_ip<<<Tc, 128>>>(pqc, g_postq, LATc);
    rms_ip<<<Tc, 128>>>(pkc, g_postk, KVDc);

    // 6) per-head L2 norm + RoPE (attn scale folded into q)
    headnorm_rope<<<(Tc * NHc) / 128, 128>>>(pqc, LATc, key_temp, 0);
    headnorm_rope<<<(Tc * NKVc) / 128, 128>>>(pkc, KVDc, key_temp, 1);

    // 7) causal attention
    flash_attn<<<dim3(Sc / 128, Bc * NHc), 128>>>(po, pqc, pkc, pv);

    // 8) pre-out RMS + output projection
    rms_ip<<<Tc, 128>>>(po, g_preout, LATc);
    gemm_tf32<<<dim3(16, Tc / 128), 256, GEMM_SMEM>>>(
        po, LATc, w_o, out, 16, Dc, nullptr, nullptr, nullptr, nullptr);
}

// round 4
// speedup vs baseline: 2.3988x; 1.9181x over previous
#include <cuda_runtime.h>
#include <math.h>
#include <cstdint>

#define Bc   4
#define Sc   2048
#define Dc   2048
#define LATc 512
#define NHc  16
#define NKVc 4
#define HDc  32
#define KVDc 128
#define Tc   (Bc * Sc)
#define GAINc 0.25f
#define EPSc  1e-6f

// -------- scratch (device globals; no allocation allowed) --------
__device__ float g_q [Tc * LATc];
__device__ float g_k [Tc * KVDc];
__device__ float g_v [Tc * KVDc];
__device__ float g_qc[Tc * LATc];
__device__ float g_kc[Tc * KVDc];
__device__ float g_qm[Tc * HDc];
__device__ float g_km[Tc * HDc];
__device__ float g_o [Tc * LATc];

// ---------------- mma.sync helpers ----------------
__device__ __forceinline__ void mma_tf32(float* d, uint32_t a0, uint32_t a1,
                                         uint32_t a2, uint32_t a3,
                                         uint32_t b0, uint32_t b1) {
    asm volatile(
        "mma.sync.aligned.m16n8k8.row.col.f32.tf32.tf32.f32 "
        "{%0,%1,%2,%3}, {%4,%5,%6,%7}, {%8,%9}, {%0,%1,%2,%3};"
        : "+f"(d[0]), "+f"(d[1]), "+f"(d[2]), "+f"(d[3])
        : "r"(a0), "r"(a1), "r"(a2), "r"(a3), "r"(b0), "r"(b1));
}
__device__ __forceinline__ void split_tf32(float x, uint32_t& hi, uint32_t& lo) {
    uint32_t h;
    asm("cvt.rna.tf32.f32 %0, %1;" : "=r"(h) : "f"(x));
    float r = x - __uint_as_float(h);
    uint32_t l;
    asm("cvt.rna.tf32.f32 %0, %1;" : "=r"(l) : "f"(r));
    hi = h; lo = l;
}
__device__ __forceinline__ uint32_t smem_u32(const void* p) {
    uint32_t a;
    asm("{ .reg .u64 t; cvta.to.shared.u64 t, %1; cvt.u32.u64 %0, t; }" : "=r"(a) : "l"(p));
    return a;
}
#define CP_ASYNC16(dst, src) \
    asm volatile("cp.async.cg.shared.global [%0], [%1], 16;" :: "r"(dst), "l"(src))
#define CP_COMMIT() asm volatile("cp.async.commit_group;" ::: "memory")
#define CP_WAIT(n)  asm volatile("cp.async.wait_group %0;" :: "n"(n) : "memory")

// ============================================================
// tf32-split GEMM via mma.sync: C[M,N] = A[M,K]*B[N,K]^T (fp32 in/out)
// CTA tile 128x128, K-chunk 32, 3-stage cp.async pipeline.
// ============================================================
#define TSTRIDE 36
#define ABYTES  (128 * TSTRIDE * 4)      // 18432
#define BUFB    (2 * ABYTES)             // A + B per stage
#define GEMM_SMEM (3 * BUFB)             // three stages: 110592 B

__global__ void __launch_bounds__(256, 1) gemm_tf32(
    const float* __restrict__ A, int K,
    const float* __restrict__ B0, float* __restrict__ C0, int nx0, int N0,
    const float* __restrict__ B1, float* __restrict__ C1,
    const float* __restrict__ B2, float* __restrict__ C2)
{
    extern __shared__ char sm[];
    const int tid = threadIdx.x;
    const int wid = tid >> 5;
    const int lane = tid & 31;
    const int lr = lane >> 2;
    const int lc = lane & 3;
    const int wm = wid & 3;
    const int wn = wid >> 2;

    int bx = blockIdx.x;
    const float* Bp;
    float* Cp;
    int N;
    if (bx < nx0)       { Bp = B0; Cp = C0; N = N0; }
    else if (bx == nx0) { Bp = B1; Cp = C1; N = 128; bx = 0; }
    else                { Bp = B2; Cp = C2; N = 128; bx = 0; }
    const int m0 = blockIdx.y * 128;
    const int n0 = bx * 128;
    const int NC = K >> 5;

    const uint32_t smb = smem_u32(sm);
    int grow[4], gc16[4];
    uint32_t sdst[4];
#pragma unroll
    for (int j = 0; j < 4; j++) {
        int seg = tid + j * 256;
        grow[j] = seg >> 3;
        gc16[j] = seg & 7;
        sdst[j] = (uint32_t)(grow[j] * (TSTRIDE * 4) + gc16[j] * 16);
    }

    float acc[2][8][4];
#pragma unroll
    for (int mt = 0; mt < 2; mt++)
#pragma unroll
        for (int nt = 0; nt < 8; nt++)
#pragma unroll
            for (int c = 0; c < 4; c++) acc[mt][nt][c] = 0.f;

    // prefetch chunks 0 and 1
#pragma unroll
    for (int pc = 0; pc < 2; pc++) {
        const uint32_t so = smb + (uint32_t)pc * BUFB;
        const int kt = pc << 5;
#pragma unroll
        for (int j = 0; j < 4; j++) {
            CP_ASYNC16(so + sdst[j], A + (size_t)(m0 + grow[j]) * K + kt + gc16[j] * 4);
            CP_ASYNC16(so + ABYTES + sdst[j], Bp + (size_t)(n0 + grow[j]) * K + kt + gc16[j] * 4);
        }
        CP_COMMIT();
    }

    int bufi = 0;            // i % 3
    for (int i = 0; i < NC; i++) {
        if (i + 2 < NC) {
            int dsti = bufi + 2; if (dsti >= 3) dsti -= 3;
            const uint32_t so = smb + (uint32_t)dsti * BUFB;
            const int kt = (i + 2) << 5;
#pragma unroll
            for (int j = 0; j < 4; j++) {
                CP_ASYNC16(so + sdst[j], A + (size_t)(m0 + grow[j]) * K + kt + gc16[j] * 4);
                CP_ASYNC16(so + ABYTES + sdst[j], Bp + (size_t)(n0 + grow[j]) * K + kt + gc16[j] * 4);
            }
        }
        CP_COMMIT();         // possibly-empty group keeps the count uniform
        CP_WAIT(2);          // chunk i guaranteed complete
        __syncthreads();

        const float* Ab = (const float*)(sm + (size_t)bufi * BUFB);
        const float* Bb = (const float*)(sm + (size_t)bufi * BUFB + ABYTES);

#pragma unroll
        for (int ks = 0; ks < 4; ks++) {
            const int kc = ks * 8 + lc;
            uint32_t ah[2][4], al[2][4];
#pragma unroll
            for (int mt = 0; mt < 2; mt++) {
                const int r = wm * 32 + mt * 16 + lr;
                split_tf32(Ab[r * TSTRIDE + kc],           ah[mt][0], al[mt][0]);
                split_tf32(Ab[(r + 8) * TSTRIDE + kc],     ah[mt][1], al[mt][1]);
                split_tf32(Ab[r * TSTRIDE + kc + 4],       ah[mt][2], al[mt][2]);
                split_tf32(Ab[(r + 8) * TSTRIDE + kc + 4], ah[mt][3], al[mt][3]);
            }
            uint32_t bh[8][2], bl[8][2];
#pragma unroll
            for (int nt = 0; nt < 8; nt++) {
                const int n = wn * 64 + nt * 8 + lr;
                split_tf32(Bb[n * TSTRIDE + kc],     bh[nt][0], bl[nt][0]);
                split_tf32(Bb[n * TSTRIDE + kc + 4], bh[nt][1], bl[nt][1]);
            }
#pragma unroll
            for (int mt = 0; mt < 2; mt++)
#pragma unroll
                for (int nt = 0; nt < 8; nt++) {
                    mma_tf32(acc[mt][nt], ah[mt][0], ah[mt][1], ah[mt][2], ah[mt][3],
                             bh[nt][0], bh[nt][1]);
                    mma_tf32(acc[mt][nt], ah[mt][0], ah[mt][1], ah[mt][2], ah[mt][3],
                             bl[nt][0], bl[nt][1]);
                    mma_tf32(acc[mt][nt], al[mt][0], al[mt][1], al[mt][2], al[mt][3],
                             bh[nt][0], bh[nt][1]);
                }
        }
        __syncthreads();
        if (++bufi == 3) bufi = 0;
    }

#pragma unroll
    for (int mt = 0; mt < 2; mt++) {
        const int r = m0 + wm * 32 + mt * 16 + lr;
#pragma unroll
        for (int nt = 0; nt < 8; nt++) {
            const int cN = n0 + wn * 64 + nt * 8 + 2 * lc;
            *(float2*)(Cp + (size_t)r * N + cN) =
                make_float2(acc[mt][nt][0], acc[mt][nt][1]);
            *(float2*)(Cp + (size_t)(r + 8) * N + cN) =
                make_float2(acc[mt][nt][2], acc[mt][nt][3]);
        }
    }
}

// ============================================================
// In-place RMS norm over last dim C, one block per row
// ============================================================
__global__ void __launch_bounds__(128) rms_ip(
    float* __restrict__ x, const float* __restrict__ g, int C)
{
    const int t = blockIdx.x;
    float* row = x + (size_t)t * C;
    const int tid = threadIdx.x;
    float ss = 0.f;
    for (int i = tid; i < C; i += 128) { float v = row[i]; ss += v * v; }
#pragma unroll
    for (int o = 16; o; o >>= 1) ss += __shfl_xor_sync(~0u, ss, o);
    __shared__ float ws[4];
    if ((tid & 31) == 0) ws[tid >> 5] = ss;
    __syncthreads();
    float tot = ws[0] + ws[1] + ws[2] + ws[3];
    float r = rsqrtf(tot / (float)C + EPSc);
    for (int i = tid; i < C; i += 128) row[i] = row[i] * r * g[i];
}

// ============================================================
// Grouped causal conv, K=3, 32 in/out channels per group.
// Tiled: block = (64 tokens) x (32-channel group).
// Weights staged in smem [96][33] (coalesced load, conflict-free read);
// x tile [66][32] (broadcast read).
// ============================================================
__global__ void __launch_bounds__(256) conv_causal_t(
    float* __restrict__ y, const float* __restrict__ x,
    const float* __restrict__ w, int C)
{
    __shared__ float ws[96][33];
    __shared__ float xs[66][32];
    const int tid = threadIdx.x;
    const int t0 = blockIdx.x * 64;
    const int base = blockIdx.y * 32;
    const int s0 = t0 & (Sc - 1);

    // weights: ws[r][co] = w[(base+co)*96 + r], r = ci*3 + j
    for (int idx = tid; idx < 3072; idx += 256) {
        int co = idx / 96;
        int r = idx - co * 96;
        ws[r][co] = w[(size_t)(base + co) * 96 + r];
    }
    // x tile: rows 0..65 <-> tokens t0-2 .. t0+63 (zero before sequence start)
    for (int idx = tid; idx < 66 * 32; idx += 256) {
        int row = idx >> 5;
        int ci = idx & 31;
        int srow = s0 - 2 + row;
        xs[row][ci] = (srow >= 0 && row < 66)
            ? x[(size_t)(t0 - 2 + row) * C + base + ci] : 0.f;
    }
    __syncthreads();

    const int co = tid & 31;
    const int tg = tid >> 5;     // 0..7
#pragma unroll
    for (int tk = 0; tk < 8; tk++) {
        const int tt = tg * 8 + tk;
        float acc = 0.f;
#pragma unroll 8
        for (int ci = 0; ci < 32; ci++) {
#pragma unroll
            for (int j = 0; j < 3; j++)
                acc += ws[ci * 3 + j][co] * xs[tt + j][ci];
        }
        y[(size_t)(t0 + tt) * C + base + co] = acc;
    }
}

// ============================================================
// Per-token head-mean: out[t][d] = mean_h x[t][h*32+d]
// ============================================================
__global__ void __launch_bounds__(256) head_mean(
    float* __restrict__ out, const float* __restrict__ x, int C, int heads)
{
    const int idx = blockIdx.x * 256 + threadIdx.x;
    if (idx >= Tc * HDc) return;
    const int t = idx >> 5;
    const int d = idx & 31;
    const float* row = x + (size_t)t * C + d;
    float s = 0.f;
    for (int h = 0; h < heads; h++) s += row[h * 32];
    out[idx] = s / (float)heads;
}

__global__ void __launch_bounds__(256) add_mean(
    float* __restrict__ x, const float* __restrict__ mean, int C)
{
    const int idx = blockIdx.x * 256 + threadIdx.x;
    const int t = idx / C;
    if (t >= Tc) return;
    const int d = idx & 31;
    x[idx] += GAINc * mean[(t << 5) + d];
}

// ============================================================
// Per-head L2 normalize (+temp) then RoPE, in place.
// ============================================================
__global__ void __launch_bounds__(128) headnorm_rope(
    float* __restrict__ x, int C, const float* __restrict__ key_temp, int is_k)
{
    const int nh = C >> 5;
    const int idx = blockIdx.x * 128 + threadIdx.x;
    const int t = idx / nh;
    if (t >= Tc) return;
    const int h = idx - t * nh;
    const int s = t & (Sc - 1);
    float* p = x + (size_t)t * C + h * 32;
    float v[32];
    float ss = 0.f;
#pragma unroll
    for (int d = 0; d < 32; d++) { v[d] = p[d]; ss += v[d] * v[d]; }
    float n = fmaxf(sqrtf(ss), 1e-12f);
    float f = is_k ? (5.656854249492380f * key_temp[0] / n) : (1.0f / n);
#pragma unroll
    for (int d = 0; d < 32; d++) v[d] *= f;
#pragma unroll
    for (int i = 0; i < 16; i++) {
        float fr = expf(-(float)i * 0.575646273248511f);
        float ang = (float)s * fr;
        float sn, cs;
        sincosf(ang, &sn, &cs);
        float x1 = v[2 * i], x2 = v[2 * i + 1];
        v[2 * i]     = x1 * cs - x2 * sn;
        v[2 * i + 1] = x1 * sn + x2 * cs;
    }
#pragma unroll
    for (int d = 0; d < 32; d++) p[d] = v[d];
}

// ============================================================
// Flash-style causal attention (GQA 16 q-heads -> 4 kv-heads)
// float4-vectorized smem tiles to cut LDS issue slots 4x.
// ============================================================
__global__ void __launch_bounds__(128) flash_attn(
    float* __restrict__ o, const float* __restrict__ q,
    const float* __restrict__ k, const float* __restrict__ v)
{
    __shared__ float4 Ks[32][8];
    __shared__ float4 Vs[32][8];
    const int bh = blockIdx.y;
    const int b = bh / NHc;
    const int h = bh - b * NHc;
    const int kh = h >> 2;
    const int tid = threadIdx.x;
    const int sq = blockIdx.x * 128 + tid;

    float4 q4[8];
    {
        const float4* qp = (const float4*)(q + (size_t)(b * Sc + sq) * LATc + h * 32);
#pragma unroll
        for (int d = 0; d < 8; d++) q4[d] = qp[d];
    }
    float4 oa[8];
#pragma unroll
    for (int d = 0; d < 8; d++) oa[d] = make_float4(0.f, 0.f, 0.f, 0.f);
    float m = -1e30f, l = 0.f;

    const int maxs = blockIdx.x * 128 + 127;
    const int ntiles = (maxs >> 5) + 1;

    for (int jt = 0; jt < ntiles; jt++) {
        const int j0 = jt << 5;
        __syncthreads();
        for (int u = tid; u < 256; u += 128) {
            int jj = u >> 3, d = u & 7;
            size_t gi = (size_t)(b * Sc + j0 + jj) * KVDc + kh * 32 + d * 4;
            Ks[jj][d] = *(const float4*)(k + gi);
            Vs[jj][d] = *(const float4*)(v + gi);
        }
        __syncthreads();
        if (j0 <= sq) {
            const bool full = (j0 + 31) <= sq;
            float sc[32];
#pragma unroll
            for (int j = 0; j < 32; j++) {
                float s = 0.f;
#pragma unroll
                for (int d = 0; d < 8; d++) {
                    float4 kv = Ks[j][d];
                    s += q4[d].x * kv.x + q4[d].y * kv.y
                       + q4[d].z * kv.z + q4[d].w * kv.w;
                }
                sc[j] = s;
            }
            if (!full) {
#pragma unroll
                for (int j = 0; j < 32; j++)
                    if (j0 + j > sq) sc[j] = -1e30f;
            }
            float tm = m;
#pragma unroll
            for (int j = 0; j < 32; j++) tm = fmaxf(tm, sc[j]);
            float alpha = __expf(m - tm);
            m = tm;
            l *= alpha;
#pragma unroll
            for (int d = 0; d < 8; d++) {
                oa[d].x *= alpha; oa[d].y *= alpha;
                oa[d].z *= alpha; oa[d].w *= alpha;
            }
#pragma unroll
            for (int j = 0; j < 32; j++) {
                float p = __expf(sc[j] - m);
                l += p;
#pragma unroll
                for (int d = 0; d < 8; d++) {
                    float4 vv = Vs[j][d];
                    oa[d].x += p * vv.x; oa[d].y += p * vv.y;
                    oa[d].z += p * vv.z; oa[d].w += p * vv.w;
                }
            }
        }
    }

    float inv = 1.0f / l;
    float4* op = (float4*)(o + (size_t)(b * Sc + sq) * LATc + h * 32);
#pragma unroll
    for (int d = 0; d < 8; d++) {
        op[d] = make_float4(oa[d].x * inv, oa[d].y * inv,
                            oa[d].z * inv, oa[d].w * inv);
    }
}

// ============================================================
// host launcher
// ============================================================
extern "C" void kernel_launch(void* const* d_in, const int* in_sizes, int n_in,
                              void* d_out, int out_size)
{
    const float* x        = (const float*)d_in[0];
    const float* w_q      = (const float*)d_in[1];
    const float* w_k      = (const float*)d_in[2];
    const float* w_v      = (const float*)d_in[3];
    const float* g_latent = (const float*)d_in[4];
    const float* g_kv     = (const float*)d_in[5];
    const float* conv_q_w = (const float*)d_in[6];
    const float* conv_k_w = (const float*)d_in[7];
    const float* g_conv   = (const float*)d_in[8];
    const float* g_kconv  = (const float*)d_in[9];
    const float* g_postq  = (const float*)d_in[10];
    const float* g_postk  = (const float*)d_in[11];
    const float* key_temp = (const float*)d_in[12];
    const float* g_preout = (const float*)d_in[13];
    const float* w_o      = (const float*)d_in[14];
    float* out = (float*)d_out;

    float *pq, *pk, *pv, *pqc, *pkc, *pqm, *pkm, *po;
    cudaGetSymbolAddress((void**)&pq,  g_q);
    cudaGetSymbolAddress((void**)&pk,  g_k);
    cudaGetSymbolAddress((void**)&pv,  g_v);
    cudaGetSymbolAddress((void**)&pqc, g_qc);
    cudaGetSymbolAddress((void**)&pkc, g_kc);
    cudaGetSymbolAddress((void**)&pqm, g_qm);
    cudaGetSymbolAddress((void**)&pkm, g_km);
    cudaGetSymbolAddress((void**)&po,  g_o);

    cudaFuncSetAttribute(gemm_tf32, cudaFuncAttributeMaxDynamicSharedMemorySize, GEMM_SMEM);

    // 1) fused q/k/v projections
    gemm_tf32<<<dim3(6, Tc / 128), 256, GEMM_SMEM>>>(
        x, Dc, w_q, pq, 4, LATc, w_k, pk, w_v, pv);

    // 2) first RMS norms
    rms_ip<<<Tc, 128>>>(pq, g_latent, LATc);
    rms_ip<<<Tc, 128>>>(pk, g_kv, KVDc);
    rms_ip<<<Tc, 128>>>(pv, g_kv, KVDc);

    // 3) causal grouped conv + RMS
    conv_causal_t<<<dim3(Tc / 64, LATc / 32), 256>>>(pqc, pq, conv_q_w, LATc);
    conv_causal_t<<<dim3(Tc / 64, KVDc / 32), 256>>>(pkc, pk, conv_k_w, KVDc);
    rms_ip<<<Tc, 128>>>(pqc, g_conv, LATc);
    rms_ip<<<Tc, 128>>>(pkc, g_kconv, KVDc);

    // 4) cross-coupling means (from pre-conv q/k)
    head_mean<<<(Tc * HDc) / 256, 256>>>(pqm, pq, LATc, NHc);
    head_mean<<<(Tc * HDc) / 256, 256>>>(pkm, pk, KVDc, NKVc);
    add_mean<<<(Tc * LATc) / 256, 256>>>(pqc, pkm, LATc);
    add_mean<<<(Tc * KVDc) / 256, 256>>>(pkc, pqm, KVDc);

    // 5) post RMS
    rms_ip<<<Tc, 128>>>(pqc, g_postq, LATc);
    rms_ip<<<Tc, 128>>>(pkc, g_postk, KVDc);

    // 6) per-head L2 norm + RoPE (attn scale folded into q)
    headnorm_rope<<<(Tc * NHc) / 128, 128>>>(pqc, LATc, key_temp, 0);
    headnorm_rope<<<(Tc * NKVc) / 128, 128>>>(pkc, KVDc, key_temp, 1);

    // 7) causal attention
    flash_attn<<<dim3(Sc / 128, Bc * NHc), 128>>>(po, pqc, pkc, pv);

    // 8) pre-out RMS + output projection
    rms_ip<<<Tc, 128>>>(po, g_preout, LATc);
    gemm_tf32<<<dim3(16, Tc / 128), 256, GEMM_SMEM>>>(
        po, LATc, w_o, out, 16, Dc, nullptr, nullptr, nullptr, nullptr);
}